// round 14
// baseline (speedup 1.0000x reference)
#include <cuda_runtime.h>
#include <cuda_fp16.h>
#include <cstdint>

#define NS 8          // tokens per node
#define DD 128        // model dim
#define NH 4          // heads
#define DH 32         // head dim

#define MAXN 20000
#define MAXM (MAXN * NS)          // 160000 rows
#define MAXE 100000

// -------- device scratch (allocation-free rule: __device__ globals) --------
__device__ float  g_dstproj[3][MAXM * 384];   // [q|k|v] per dst-node token (fp32)
__device__ __half g_srcproj[3][MAXM * 256];   // [k|v] per src-node token (fp16)
__device__ __half g_sum[3][MAXM * DD];        // pre-Wo segment sum (fp16)
__device__ float  g_cnt[3][MAXN];
__device__ __half g_Wf[3][256 * DD];          // folded [Wk@Wb ; Wv@Wb] (fp16)
__device__ float  g_bf[3][256];               // folded biases (fp32)
__device__ int    g_hist[3][MAXN];
__device__ int    g_off[3][MAXN + 1];
__device__ int    g_cur[3][MAXN];
__device__ int    g_csr[3][MAXE];             // src node per edge, grouped by dst
// fp16 operand tables
__device__ __half g_xah[MAXM * DD];           // half(x_a)
__device__ __half g_xbh[MAXM * DD];           // half(x_b)
__device__ __half g_Wh[3][384 * DD];          // half(Win)
__device__ __half g_Woh[3][DD * DD];          // half(Wo)

// ---------------------------------------------------------------------------
// convert n4*4 floats to fp16 (rn)
__global__ void half_kernel(const float* __restrict__ in, __half* __restrict__ out, int n4) {
    int i = blockIdx.x * blockDim.x + threadIdx.x;
    if (i < n4) {
        float4 v = ((const float4*)in)[i];
        __half2 h0 = __floats2half2_rn(v.x, v.y);
        __half2 h1 = __floats2half2_rn(v.z, v.w);
        uint2 pk;
        pk.x = *(uint32_t*)&h0;
        pk.y = *(uint32_t*)&h1;
        ((uint2*)out)[i] = pk;
    }
}

__global__ void zero2_int_kernel(int* __restrict__ a, int* __restrict__ b, int n) {
    int i = blockIdx.x * blockDim.x + threadIdx.x;
    if (i < n) { a[i] = 0; b[i] = 0; }
}

__global__ void hist_kernel(const int* __restrict__ ei, int E, int* __restrict__ hist) {
    int i = blockIdx.x * blockDim.x + threadIdx.x;
    if (i < E) atomicAdd(hist + ei[E + i], 1);
}

__global__ __launch_bounds__(1024)
void scan_kernel(const int* __restrict__ hist, int* __restrict__ off, int N) {
    __shared__ int part[1025];
    const int t = threadIdx.x;
    const int chunk = (N + 1023) >> 10;
    const int lo = t * chunk;
    const int hi = min(lo + chunk, N);
    int s = 0;
    for (int i = lo; i < hi; i++) s += hist[i];
    part[t] = s;
    __syncthreads();
    if (t == 0) {
        int acc = 0;
        for (int i = 0; i < 1024; i++) { int v = part[i]; part[i] = acc; acc += v; }
        part[1024] = acc;
        off[N] = acc;
    }
    __syncthreads();
    int acc = part[t];
    for (int i = lo; i < hi; i++) { off[i] = acc; acc += hist[i]; }
}

__global__ void scatter_kernel(const int* __restrict__ ei, int E,
                               const int* __restrict__ off, int* __restrict__ cur,
                               int* __restrict__ csr) {
    int i = blockIdx.x * blockDim.x + threadIdx.x;
    if (i < E) {
        int dst = ei[E + i];
        int pos = atomicAdd(cur + dst, 1);
        csr[off[dst] + pos] = ei[i];
    }
}

__global__ void cnt_kernel(const int* __restrict__ off, float* __restrict__ cnt, int N) {
    int i = blockIdx.x * blockDim.x + threadIdx.x;
    if (i < N) cnt[i] = (float)(off[i + 1] - off[i]);
}

// Fold Wb into K/V projections: Wf[o,d] = half(sum_j Win[128+o, j] * Wb[j, d])
__global__ void fold_kernel(const float* __restrict__ Win, const float* __restrict__ Wb,
                            const float* __restrict__ bb, const float* __restrict__ bin,
                            __half* __restrict__ Wf, float* __restrict__ bf) {
    int id = blockIdx.x * blockDim.x + threadIdx.x;
    int o = id >> 7, d = id & 127;
    const float* wrow = Win + (size_t)(128 + o) * DD;
    float acc = 0.f;
    #pragma unroll 8
    for (int j = 0; j < DD; j++) acc += wrow[j] * Wb[j * DD + d];
    Wf[o * DD + d] = __float2half_rn(acc);
    if (d == 0) {
        float b = 0.f;
        for (int j = 0; j < DD; j++) b += wrow[j] * bb[j];
        bf[o] = b + bin[128 + o];
    }
}

// ---------------------------------------------------------------------------
__device__ __forceinline__ void cp_async16(void* smem, const void* gmem) {
    uint32_t s = (uint32_t)__cvta_generic_to_shared(smem);
    asm volatile("cp.async.cg.shared.global [%0], [%1], 16;" :: "r"(s), "l"(gmem));
}
__device__ __forceinline__ void cp_commit() {
    asm volatile("cp.async.commit_group;");
}
template <int N> __device__ __forceinline__ void cp_wait() {
    asm volatile("cp.async.wait_group %0;" :: "n"(N));
}

// C[M, Nout] = alpha * ( rowscale * (A @ B^T) + bpresent*bias ), optionally +=.
// A, B fp16; fp32 accumulate via mma.m16n8k16. 128x128 block tile, 8 warps in
// 2x4 (warp tile 64x32 = 4x4 mma tiles). cp.async double buffer, 4 k-chunks.
// Epilogue fp32: rowscale/bias/alpha; fp32 or fp16 output.
__global__ __launch_bounds__(256)
void gemm_f16(const __half* __restrict__ A, const __half* __restrict__ B,
              const float* __restrict__ bias, void* __restrict__ Cv,
              int ldc, const float* __restrict__ cnt,
              float alpha, int accumulate, int out_half) {
    __shared__ __half As[2][128][40];   // stride 40 halfs = 80 B (conflict-free)
    __shared__ __half Bs[2][128][40];

    const int t    = threadIdx.x;
    const int lane = t & 31;
    const int warp = t >> 5;
    const int wm   = warp >> 2;          // 0..1 -> 64-row slice
    const int wn   = warp & 3;           // 0..3 -> 32-col slice
    const int m0   = blockIdx.y * 128;
    const int n0   = blockIdx.x * 128;
    const int lg   = lane >> 2;          // groupID 0..7
    const int lt   = lane & 3;           // tid-in-group 0..3

    float acc[4][4][4] = {};             // [mtile][ntile][c]

    auto load_stage = [&](int ks) {
        const int k0 = ks * 32;
        const int b  = ks & 1;
        // A: 128 rows x 32 halfs = 512 16B-chunks, 2 per thread
        #pragma unroll
        for (int r = 0; r < 2; r++) {
            int idx = t + r * 256;
            int row = idx >> 2, c4 = idx & 3;
            cp_async16(&As[b][row][c4 * 8],
                       A + (size_t)(m0 + row) * DD + k0 + c4 * 8);
        }
        // B: 128 rows x 32 halfs = 512 chunks, 2 per thread
        #pragma unroll
        for (int r = 0; r < 2; r++) {
            int idx = t + r * 256;
            int row = idx >> 2, c4 = idx & 3;
            cp_async16(&Bs[b][row][c4 * 8],
                       B + (size_t)(n0 + row) * DD + k0 + c4 * 8);
        }
        cp_commit();
    };

    load_stage(0);

    #pragma unroll
    for (int kc = 0; kc < 4; kc++) {
        if (kc < 3) { load_stage(kc + 1); cp_wait<1>(); }
        else        { cp_wait<0>(); }
        __syncthreads();

        const int b = kc & 1;
        #pragma unroll
        for (int ks = 0; ks < 2; ks++) {
            const int kk = ks * 16;
            uint32_t af[4][4], bfr[4][2];
            #pragma unroll
            for (int mt = 0; mt < 4; mt++) {
                int rbase = wm * 64 + mt * 16;
                af[mt][0] = *(const uint32_t*)&As[b][rbase + lg][kk + 2 * lt];
                af[mt][1] = *(const uint32_t*)&As[b][rbase + 8 + lg][kk + 2 * lt];
                af[mt][2] = *(const uint32_t*)&As[b][rbase + lg][kk + 8 + 2 * lt];
                af[mt][3] = *(const uint32_t*)&As[b][rbase + 8 + lg][kk + 8 + 2 * lt];
            }
            #pragma unroll
            for (int nt = 0; nt < 4; nt++) {
                int nrow = wn * 32 + nt * 8 + lg;
                bfr[nt][0] = *(const uint32_t*)&Bs[b][nrow][kk + 2 * lt];
                bfr[nt][1] = *(const uint32_t*)&Bs[b][nrow][kk + 8 + 2 * lt];
            }
            #pragma unroll
            for (int mt = 0; mt < 4; mt++) {
                #pragma unroll
                for (int nt = 0; nt < 4; nt++) {
                    asm volatile(
                        "mma.sync.aligned.m16n8k16.row.col.f32.f16.f16.f32 "
                        "{%0,%1,%2,%3}, {%4,%5,%6,%7}, {%8,%9}, {%0,%1,%2,%3};"
                        : "+f"(acc[mt][nt][0]), "+f"(acc[mt][nt][1]),
                          "+f"(acc[mt][nt][2]), "+f"(acc[mt][nt][3])
                        : "r"(af[mt][0]), "r"(af[mt][1]), "r"(af[mt][2]), "r"(af[mt][3]),
                          "r"(bfr[nt][0]), "r"(bfr[nt][1]));
                }
            }
        }
        __syncthreads();
    }

    #pragma unroll
    for (int mt = 0; mt < 4; mt++) {
        int r0 = m0 + wm * 64 + mt * 16 + lg;
        int r1 = r0 + 8;
        float bp0 = 1.f, bp1 = 1.f, rs0 = 1.f, rs1 = 1.f;
        if (cnt) {
            float c0 = cnt[r0 >> 3], c1 = cnt[r1 >> 3];
            bp0 = (c0 > 0.f) ? 1.f : 0.f;  rs0 = (c0 > 0.f) ? (1.f / c0) : 0.f;
            bp1 = (c1 > 0.f) ? 1.f : 0.f;  rs1 = (c1 > 0.f) ? (1.f / c1) : 0.f;
        }
        #pragma unroll
        for (int nt = 0; nt < 4; nt++) {
            int col = n0 + wn * 32 + nt * 8 + 2 * lt;
            float b0 = bias[col], b1 = bias[col + 1];
            float v00 = alpha * (rs0 * acc[mt][nt][0] + bp0 * b0);
            float v01 = alpha * (rs0 * acc[mt][nt][1] + bp0 * b1);
            float v10 = alpha * (rs1 * acc[mt][nt][2] + bp1 * b0);
            float v11 = alpha * (rs1 * acc[mt][nt][3] + bp1 * b1);
            if (out_half) {
                __half* C = (__half*)Cv;
                *(__half2*)(C + (size_t)r0 * ldc + col) = __floats2half2_rn(v00, v01);
                *(__half2*)(C + (size_t)r1 * ldc + col) = __floats2half2_rn(v10, v11);
            } else {
                float* C = (float*)Cv;
                float* p0 = C + (size_t)r0 * ldc + col;
                float* p1 = C + (size_t)r1 * ldc + col;
                if (accumulate) {
                    p0[0] += v00; p0[1] += v01;
                    p1[0] += v10; p1[1] += v11;
                } else {
                    *(float2*)p0 = make_float2(v00, v01);
                    *(float2*)p1 = make_float2(v10, v11);
                }
            }
        }
    }
}

// ---------------------------------------------------------------------------
// (R12 winner) One block per dst node. dst q/k/v fp32 staged once. src k/v
// fp16 through a 3-buffer cp.async ring with ONE barrier per edge.
#define SORT_CAP 128
#define HROW 136   // half row stride: 272 B = 17*16B (cp.async-aligned)
__global__ __launch_bounds__(128)
void node_attn_kernel(const int* __restrict__ off, const int* __restrict__ csr,
                      const float* __restrict__ dstproj,
                      const __half* __restrict__ srcproj,
                      __half* __restrict__ gsum) {
    __shared__ float  sq[8][132];
    __shared__ float  skd[8][132];
    __shared__ float  svd[8][132];
    __shared__ __half sks[3][8][HROW];
    __shared__ __half svs[3][8][HROW];
    __shared__ int    elist[SORT_CAP];

    const int n = blockIdx.x;
    const int t = threadIdx.x;
    const int off0 = off[n];
    const int deg  = off[n + 1] - off0;
    if (deg == 0) return;

    const bool cached = (deg <= SORT_CAP);
    if (cached) {
        for (int i = t; i < deg; i += 128) elist[i] = csr[off0 + i];
        __syncthreads();
        if (t == 0) {
            for (int i = 1; i < deg; i++) {
                int v = elist[i], j = i - 1;
                while (j >= 0 && elist[j] > v) { elist[j + 1] = elist[j]; j--; }
                elist[j + 1] = v;
            }
        }
    }

    const float* dp = dstproj + (size_t)n * (NS * 384);
    for (int i = t; i < 256; i += 128) {
        int s = i >> 5, c = i & 31;
        *(float4*)(&sq[s][c * 4])  = *(const float4*)(dp + s * 384 + c * 4);
        *(float4*)(&skd[s][c * 4]) = *(const float4*)(dp + s * 384 + 128 + c * 4);
        *(float4*)(&svd[s][c * 4]) = *(const float4*)(dp + s * 384 + 256 + c * 4);
    }
    __syncthreads();

    const int p  = t >> 2;     // (head, query) pair 0..31
    const int h  = p >> 3;
    const int qi = p & 7;
    const int g  = t & 3;
    const float scale = 0.17677669529663687f;   // 1/sqrt(32)

    float4 qr[8];
    #pragma unroll
    for (int u = 0; u < 8; u++) qr[u] = *(float4*)(&sq[qi][h * DH + u * 4]);

    float ldl[2];
    #pragma unroll
    for (int j = 0; j < 2; j++) {
        int kk = g + j * 4;
        float acc = 0.f;
        #pragma unroll
        for (int u = 0; u < 8; u++) {
            float4 kr = *(float4*)(&skd[kk][h * DH + u * 4]);
            acc += qr[u].x * kr.x + qr[u].y * kr.y + qr[u].z * kr.z + qr[u].w * kr.w;
        }
        ldl[j] = acc * scale;
    }

    float o[8];
    #pragma unroll
    for (int d = 0; d < 8; d++) o[d] = 0.f;

    const int srow = t >> 4;         // 0..7
    const int schk = t & 15;         // 0..15 (16B chunks of 8 halfs)
    auto stage = [&](int e) {
        int sn = cached ? elist[e] : csr[off0 + e];
        const __half* sp = srcproj + (size_t)sn * (NS * 256);
        const int b = e % 3;
        cp_async16(&sks[b][srow][schk * 8], sp + srow * 256 + schk * 8);
        cp_async16(&svs[b][srow][schk * 8], sp + srow * 256 + 128 + schk * 8);
        cp_commit();
    };

    stage(0);
    if (deg > 1) stage(1);

    const int lbase = (t & 31) & ~3;
    for (int e = 0; e < deg; e++) {
        const int b = e % 3;
        if (e + 1 < deg) cp_wait<1>(); else cp_wait<0>();
        __syncthreads();
        if (e + 2 < deg) stage(e + 2);   // overwrites (e-1)%3 — safe post-barrier

        float l[4];
        l[0] = ldl[0]; l[1] = ldl[1];
        #pragma unroll
        for (int j = 0; j < 2; j++) {
            int kk = g + j * 4;
            const __half* kp = &sks[b][kk][h * DH];
            float acc = 0.f;
            #pragma unroll
            for (int u = 0; u < 8; u++) {
                float2 k0 = __half22float2(*(const __half2*)(kp + u * 4 + 0));
                float2 k1 = __half22float2(*(const __half2*)(kp + u * 4 + 2));
                acc += qr[u].x * k0.x + qr[u].y * k0.y + qr[u].z * k1.x + qr[u].w * k1.y;
            }
            l[2 + j] = acc * scale;
        }

        float m = fmaxf(fmaxf(l[0], l[1]), fmaxf(l[2], l[3]));
        m = fmaxf(m, __shfl_xor_sync(0xffffffffu, m, 1));
        m = fmaxf(m, __shfl_xor_sync(0xffffffffu, m, 2));
        float pr[4], es = 0.f;
        #pragma unroll
        for (int j = 0; j < 4; j++) { pr[j] = __expf(l[j] - m); es += pr[j]; }
        es += __shfl_xor_sync(0xffffffffu, es, 1);
        es += __shfl_xor_sync(0xffffffffu, es, 2);
        float inv = 1.f / es;
        float att[4];
        #pragma unroll
        for (int j = 0; j < 4; j++) att[j] = pr[j] * inv;

        #pragma unroll
        for (int kk = 0; kk < 8; kk++) {
            float a = __shfl_sync(0xffffffffu, att[kk >> 2], lbase | (kk & 3));
            const float* vr = &svd[kk][h * DH + g * 8];
            #pragma unroll
            for (int d = 0; d < 8; d++) o[d] += a * vr[d];
        }
        #pragma unroll
        for (int kk = 8; kk < 16; kk++) {
            float a = __shfl_sync(0xffffffffu, att[kk >> 2], lbase | (kk & 3));
            const __half* vr = &svs[b][kk - 8][h * DH + g * 8];
            #pragma unroll
            for (int j = 0; j < 4; j++) {
                float2 v = __half22float2(*(const __half2*)(vr + j * 2));
                o[j * 2 + 0] += a * v.x;
                o[j * 2 + 1] += a * v.y;
            }
        }
    }

    __half* outp = gsum + (size_t)n * (NS * DD) + qi * DD + h * DH + g * 8;
    __half2 hs[4];
    hs[0] = __floats2half2_rn(o[0], o[1]);
    hs[1] = __floats2half2_rn(o[2], o[3]);
    hs[2] = __floats2half2_rn(o[4], o[5]);
    hs[3] = __floats2half2_rn(o[6], o[7]);
    *(uint4*)outp = *(uint4*)hs;
}

// ---------------------------------------------------------------------------
extern "C" void kernel_launch(void* const* d_in, const int* in_sizes, int n_in,
                              void* d_out, int out_size) {
    const float* x_a = (const float*)d_in[0];
    const float* x_b = (const float*)d_in[1];
    const int* ei[3] = {(const int*)d_in[2], (const int*)d_in[3], (const int*)d_in[4]};
    const int E  = in_sizes[2] / 2;
    const int Nn = in_sizes[0] / (NS * DD);
    const int M  = Nn * NS;

    float *dstprojB, *cntB, *bfB;
    __half *srcprojB, *sumB, *WfB, *xah, *xbh, *WhB, *WohB;
    int *histB, *offB, *curB, *csrB;
    cudaGetSymbolAddress((void**)&dstprojB, g_dstproj);
    cudaGetSymbolAddress((void**)&srcprojB, g_srcproj);
    cudaGetSymbolAddress((void**)&sumB, g_sum);
    cudaGetSymbolAddress((void**)&cntB, g_cnt);
    cudaGetSymbolAddress((void**)&WfB, g_Wf);
    cudaGetSymbolAddress((void**)&bfB, g_bf);
    cudaGetSymbolAddress((void**)&histB, g_hist);
    cudaGetSymbolAddress((void**)&offB, g_off);
    cudaGetSymbolAddress((void**)&curB, g_cur);
    cudaGetSymbolAddress((void**)&csrB, g_csr);
    cudaGetSymbolAddress((void**)&xah, g_xah);
    cudaGetSymbolAddress((void**)&xbh, g_xbh);
    cudaGetSymbolAddress((void**)&WhB, g_Wh);
    cudaGetSymbolAddress((void**)&WohB, g_Woh);

    static cudaStream_t st[3] = {nullptr, nullptr, nullptr};
    static cudaEvent_t ev0 = nullptr, evDone[3] = {nullptr, nullptr, nullptr};
    static cudaEvent_t evXa = nullptr, evXb = nullptr;
    if (!st[0]) {
        for (int i = 0; i < 3; i++) {
            cudaStreamCreateWithFlags(&st[i], cudaStreamNonBlocking);
            cudaEventCreateWithFlags(&evDone[i], cudaEventDisableTiming);
        }
        cudaEventCreateWithFlags(&ev0, cudaEventDisableTiming);
        cudaEventCreateWithFlags(&evXa, cudaEventDisableTiming);
        cudaEventCreateWithFlags(&evXb, cudaEventDisableTiming);
    }

    float* out = (float*)d_out;

    const __half* xsrcH[3] = {xah, xbh, xah};
    const __half* xdstH[3] = {xbh, xah, xah};
    float* outp[3]  = {out + (size_t)M * DD, out, out};
    float alphav[3] = {1.f, 0.5f, 0.5f};
    int   accumv[3] = {0, 0, 1};

    // fork
    cudaEventRecord(ev0, 0);

    // prefix: convert x_a (st0) and x_b (st1) to fp16 concurrently
    const int n4 = M * DD / 4;
    cudaStreamWaitEvent(st[0], ev0, 0);
    half_kernel<<<(n4 + 255) / 256, 256, 0, st[0]>>>(x_a, xah, n4);
    cudaEventRecord(evXa, st[0]);
    cudaStreamWaitEvent(st[1], ev0, 0);
    half_kernel<<<(n4 + 255) / 256, 256, 0, st[1]>>>(x_b, xbh, n4);
    cudaEventRecord(evXb, st[1]);
    cudaStreamWaitEvent(st[2], ev0, 0);

    for (int r = 0; r < 3; r++) {
        cudaStream_t s = st[r];

        const float* Wb  = (const float*)d_in[5 + r * 6 + 0];
        const float* bb  = (const float*)d_in[5 + r * 6 + 1];
        const float* Win = (const float*)d_in[5 + r * 6 + 2];
        const float* bin = (const float*)d_in[5 + r * 6 + 3];
        const float* Wo  = (const float*)d_in[5 + r * 6 + 4];
        const float* bo  = (const float*)d_in[5 + r * 6 + 5];

        float*  dstproj = dstprojB + (size_t)r * (MAXM * 384);
        __half* srcproj = srcprojB + (size_t)r * (MAXM * 256);
        __half* sum     = sumB     + (size_t)r * (MAXM * DD);
        float*  cnt     = cntB     + (size_t)r * MAXN;
        __half* Wf      = WfB      + (size_t)r * (256 * DD);
        float*  bf      = bfB      + (size_t)r * 256;
        __half* Wh      = WhB      + (size_t)r * (384 * DD);
        __half* Woh     = WohB     + (size_t)r * (DD * DD);
        int*    hist    = histB    + (size_t)r * MAXN;
        int*    off     = offB     + (size_t)r * (MAXN + 1);
        int*    cur     = curB     + (size_t)r * MAXN;
        int*    csr     = csrB     + (size_t)r * MAXE;

        // ---- CSR build + weight prep (independent of x conversion) ----
        zero2_int_kernel<<<(Nn + 255) / 256, 256, 0, s>>>(hist, cur, Nn);
        hist_kernel<<<(E + 255) / 256, 256, 0, s>>>(ei[r], E, hist);
        scan_kernel<<<1, 1024, 0, s>>>(hist, off, Nn);
        scatter_kernel<<<(E + 255) / 256, 256, 0, s>>>(ei[r], E, off, cur, csr);
        cnt_kernel<<<(Nn + 255) / 256, 256, 0, s>>>(off, cnt, Nn);
        fold_kernel<<<128, 256, 0, s>>>(Win, Wb, bb, bin, Wf, bf);
        half_kernel<<<(384 * DD / 4 + 255) / 256, 256, 0, s>>>(Win, Wh, 384 * DD / 4);
        half_kernel<<<(DD * DD / 4 + 255) / 256, 256, 0, s>>>(Wo, Woh, DD * DD / 4);

        // wait for the fp16 x operands this relation needs
        if (r == 0) { cudaStreamWaitEvent(s, evXb, 0); cudaStreamWaitEvent(s, evXa, 0); }
        if (r == 1) { cudaStreamWaitEvent(s, evXa, 0); }
        if (r == 2) { cudaStreamWaitEvent(s, evXa, 0); }

        // per-node projections (dst: q|k|v -> fp32 ; src: folded k|v -> fp16)
        gemm_f16<<<dim3(3, M / 128), 256, 0, s>>>(xdstH[r], Wh, bin, dstproj, 384, nullptr, 1.f, 0, 0);
        gemm_f16<<<dim3(2, M / 128), 256, 0, s>>>(xsrcH[r], Wf, bf, srcproj, 256, nullptr, 1.f, 0, 1);

        // grouped per-node attention + direct segment sum (no atomics)
        node_attn_kernel<<<Nn, 128, 0, s>>>(off, csr, dstproj, srcproj, sum);

        // r2 accumulates into out[0] after r1's plain write
        if (r == 2) cudaStreamWaitEvent(s, evDone[1], 0);

        // mean + Wo + bias (+combine across relations)
        gemm_f16<<<dim3(1, M / 128), 256, 0, s>>>(sum, Woh, bo, outp[r], DD, cnt, alphav[r], accumv[r], 0);

        cudaEventRecord(evDone[r], s);
    }

    // join
    for (int r = 0; r < 3; r++) cudaStreamWaitEvent(0, evDone[r], 0);
}

// round 15
// speedup vs baseline: 1.1383x; 1.1383x over previous
#include <cuda_runtime.h>
#include <cuda_fp16.h>
#include <cstdint>

#define NS 8          // tokens per node
#define DD 128        // model dim
#define NH 4          // heads
#define DH 32         // head dim

#define MAXN 20000
#define MAXM (MAXN * NS)          // 160000 rows
#define MAXE 100000

// -------- device scratch (allocation-free rule: __device__ globals) --------
__device__ float  g_dstproj[3][MAXM * 384];   // [q|k|v] per dst-node token (fp32)
__device__ __half g_srcproj[3][MAXM * 256];   // [k|v] per src-node token (fp16)
__device__ __half g_sum[3][MAXM * DD];        // pre-Wo segment sum (fp16)
__device__ float  g_cnt[3][MAXN];
__device__ __half g_Wf[3][256 * DD];          // folded [Wk@Wb ; Wv@Wb] (fp16)
__device__ float  g_bf[3][256];               // folded biases (fp32)
__device__ int    g_hist[3][MAXN];
__device__ int    g_off[3][MAXN + 1];
__device__ int    g_cur[3][MAXN];
__device__ int    g_csr[3][MAXE];             // src node per edge, grouped by dst
// fp16 operand tables
__device__ __half g_xah[MAXM * DD];           // half(x_a)
__device__ __half g_xbh[MAXM * DD];           // half(x_b)
__device__ __half g_Wh[3][384 * DD];          // half(Win)
__device__ __half g_Woh[3][DD * DD];          // half(Wo)

// ---------------------------------------------------------------------------
// convert n4*4 floats to fp16 (rn)
__global__ void half_kernel(const float* __restrict__ in, __half* __restrict__ out, int n4) {
    int i = blockIdx.x * blockDim.x + threadIdx.x;
    if (i < n4) {
        float4 v = ((const float4*)in)[i];
        __half2 h0 = __floats2half2_rn(v.x, v.y);
        __half2 h1 = __floats2half2_rn(v.z, v.w);
        uint2 pk;
        pk.x = *(uint32_t*)&h0;
        pk.y = *(uint32_t*)&h1;
        ((uint2*)out)[i] = pk;
    }
}

__global__ void zero2_int_kernel(int* __restrict__ a, int* __restrict__ b, int n) {
    int i = blockIdx.x * blockDim.x + threadIdx.x;
    if (i < n) { a[i] = 0; b[i] = 0; }
}

__global__ void hist_kernel(const int* __restrict__ ei, int E, int* __restrict__ hist) {
    int i = blockIdx.x * blockDim.x + threadIdx.x;
    if (i < E) atomicAdd(hist + ei[E + i], 1);
}

__global__ __launch_bounds__(1024)
void scan_kernel(const int* __restrict__ hist, int* __restrict__ off, int N) {
    __shared__ int part[1025];
    const int t = threadIdx.x;
    const int chunk = (N + 1023) >> 10;
    const int lo = t * chunk;
    const int hi = min(lo + chunk, N);
    int s = 0;
    for (int i = lo; i < hi; i++) s += hist[i];
    part[t] = s;
    __syncthreads();
    if (t == 0) {
        int acc = 0;
        for (int i = 0; i < 1024; i++) { int v = part[i]; part[i] = acc; acc += v; }
        part[1024] = acc;
        off[N] = acc;
    }
    __syncthreads();
    int acc = part[t];
    for (int i = lo; i < hi; i++) { off[i] = acc; acc += hist[i]; }
}

__global__ void scatter_kernel(const int* __restrict__ ei, int E,
                               const int* __restrict__ off, int* __restrict__ cur,
                               int* __restrict__ csr) {
    int i = blockIdx.x * blockDim.x + threadIdx.x;
    if (i < E) {
        int dst = ei[E + i];
        int pos = atomicAdd(cur + dst, 1);
        csr[off[dst] + pos] = ei[i];
    }
}

__global__ void cnt_kernel(const int* __restrict__ off, float* __restrict__ cnt, int N) {
    int i = blockIdx.x * blockDim.x + threadIdx.x;
    if (i < N) cnt[i] = (float)(off[i + 1] - off[i]);
}

// Fold Wb into K/V projections: Wf[o,d] = half(sum_j Win[128+o, j] * Wb[j, d])
__global__ void fold_kernel(const float* __restrict__ Win, const float* __restrict__ Wb,
                            const float* __restrict__ bb, const float* __restrict__ bin,
                            __half* __restrict__ Wf, float* __restrict__ bf) {
    int id = blockIdx.x * blockDim.x + threadIdx.x;
    int o = id >> 7, d = id & 127;
    const float* wrow = Win + (size_t)(128 + o) * DD;
    float acc = 0.f;
    #pragma unroll 8
    for (int j = 0; j < DD; j++) acc += wrow[j] * Wb[j * DD + d];
    Wf[o * DD + d] = __float2half_rn(acc);
    if (d == 0) {
        float b = 0.f;
        for (int j = 0; j < DD; j++) b += wrow[j] * bb[j];
        bf[o] = b + bin[128 + o];
    }
}

// ---------------------------------------------------------------------------
__device__ __forceinline__ void cp_async16(void* smem, const void* gmem) {
    uint32_t s = (uint32_t)__cvta_generic_to_shared(smem);
    asm volatile("cp.async.cg.shared.global [%0], [%1], 16;" :: "r"(s), "l"(gmem));
}
__device__ __forceinline__ void cp_commit() {
    asm volatile("cp.async.commit_group;");
}
template <int N> __device__ __forceinline__ void cp_wait() {
    asm volatile("cp.async.wait_group %0;" :: "n"(N));
}

// C[M, Nout] = alpha * ( rowscale * (A @ B^T) + bpresent*bias ), optionally +=.
// A, B fp16; fp32 accumulate via mma.m16n8k16. 128x64 block tile, 8 warps each
// 32x32 (2 mtiles x 4 ntiles). cp.async double buffer over 4 k-chunks of 32.
// Epilogue fp32: rowscale/bias/alpha; fp32 or fp16 output.  (R10/R12 winner)
__global__ __launch_bounds__(256)
void gemm_f16(const __half* __restrict__ A, const __half* __restrict__ B,
              const float* __restrict__ bias, void* __restrict__ Cv,
              int ldc, const float* __restrict__ cnt,
              float alpha, int accumulate, int out_half) {
    __shared__ __half As[2][128][40];   // stride 40 halfs = 80 B (conflict-free)
    __shared__ __half Bs[2][64][40];

    const int t    = threadIdx.x;
    const int lane = t & 31;
    const int warp = t >> 5;
    const int wm   = warp >> 1;
    const int wn   = warp & 1;
    const int m0   = blockIdx.y * 128;
    const int n0   = blockIdx.x * 64;
    const int lg   = lane >> 2;
    const int lt   = lane & 3;

    float acc[2][4][4] = {};

    auto load_stage = [&](int ks) {
        const int k0 = ks * 32;
        const int b  = ks & 1;
        #pragma unroll
        for (int r = 0; r < 2; r++) {
            int idx = t + r * 256;
            int row = idx >> 2, c4 = idx & 3;
            cp_async16(&As[b][row][c4 * 8],
                       A + (size_t)(m0 + row) * DD + k0 + c4 * 8);
        }
        {
            int row = t >> 2, c4 = t & 3;
            cp_async16(&Bs[b][row][c4 * 8],
                       B + (size_t)(n0 + row) * DD + k0 + c4 * 8);
        }
        cp_commit();
    };

    load_stage(0);

    #pragma unroll
    for (int kc = 0; kc < 4; kc++) {
        if (kc < 3) { load_stage(kc + 1); cp_wait<1>(); }
        else        { cp_wait<0>(); }
        __syncthreads();

        const int b = kc & 1;
        #pragma unroll
        for (int ks = 0; ks < 2; ks++) {
            const int kk = ks * 16;
            uint32_t af[2][4], bfr[4][2];
            #pragma unroll
            for (int mt = 0; mt < 2; mt++) {
                int rbase = wm * 32 + mt * 16;
                af[mt][0] = *(const uint32_t*)&As[b][rbase + lg][kk + 2 * lt];
                af[mt][1] = *(const uint32_t*)&As[b][rbase + 8 + lg][kk + 2 * lt];
                af[mt][2] = *(const uint32_t*)&As[b][rbase + lg][kk + 8 + 2 * lt];
                af[mt][3] = *(const uint32_t*)&As[b][rbase + 8 + lg][kk + 8 + 2 * lt];
            }
            #pragma unroll
            for (int nt = 0; nt < 4; nt++) {
                int nrow = wn * 32 + nt * 8 + lg;
                bfr[nt][0] = *(const uint32_t*)&Bs[b][nrow][kk + 2 * lt];
                bfr[nt][1] = *(const uint32_t*)&Bs[b][nrow][kk + 8 + 2 * lt];
            }
            #pragma unroll
            for (int mt = 0; mt < 2; mt++) {
                #pragma unroll
                for (int nt = 0; nt < 4; nt++) {
                    asm volatile(
                        "mma.sync.aligned.m16n8k16.row.col.f32.f16.f16.f32 "
                        "{%0,%1,%2,%3}, {%4,%5,%6,%7}, {%8,%9}, {%0,%1,%2,%3};"
                        : "+f"(acc[mt][nt][0]), "+f"(acc[mt][nt][1]),
                          "+f"(acc[mt][nt][2]), "+f"(acc[mt][nt][3])
                        : "r"(af[mt][0]), "r"(af[mt][1]), "r"(af[mt][2]), "r"(af[mt][3]),
                          "r"(bfr[nt][0]), "r"(bfr[nt][1]));
                }
            }
        }
        __syncthreads();
    }

    #pragma unroll
    for (int mt = 0; mt < 2; mt++) {
        int r0 = m0 + wm * 32 + mt * 16 + lg;
        int r1 = r0 + 8;
        float bp0 = 1.f, bp1 = 1.f, rs0 = 1.f, rs1 = 1.f;
        if (cnt) {
            float c0 = cnt[r0 >> 3], c1 = cnt[r1 >> 3];
            bp0 = (c0 > 0.f) ? 1.f : 0.f;  rs0 = (c0 > 0.f) ? (1.f / c0) : 0.f;
            bp1 = (c1 > 0.f) ? 1.f : 0.f;  rs1 = (c1 > 0.f) ? (1.f / c1) : 0.f;
        }
        #pragma unroll
        for (int nt = 0; nt < 4; nt++) {
            int col = n0 + wn * 32 + nt * 8 + 2 * lt;
            float b0 = bias[col], b1 = bias[col + 1];
            float v00 = alpha * (rs0 * acc[mt][nt][0] + bp0 * b0);
            float v01 = alpha * (rs0 * acc[mt][nt][1] + bp0 * b1);
            float v10 = alpha * (rs1 * acc[mt][nt][2] + bp1 * b0);
            float v11 = alpha * (rs1 * acc[mt][nt][3] + bp1 * b1);
            if (out_half) {
                __half* C = (__half*)Cv;
                *(__half2*)(C + (size_t)r0 * ldc + col) = __floats2half2_rn(v00, v01);
                *(__half2*)(C + (size_t)r1 * ldc + col) = __floats2half2_rn(v10, v11);
            } else {
                float* C = (float*)Cv;
                float* p0 = C + (size_t)r0 * ldc + col;
                float* p1 = C + (size_t)r1 * ldc + col;
                if (accumulate) {
                    p0[0] += v00; p0[1] += v01;
                    p1[0] += v10; p1[1] += v11;
                } else {
                    *(float2*)p0 = make_float2(v00, v01);
                    *(float2*)p1 = make_float2(v10, v11);
                }
            }
        }
    }
}

// ---------------------------------------------------------------------------
// One block per dst node. dst q/k/v staged via cp.async ISSUED FIRST so its
// ~600-cycle flight overlaps the elist load + serial sort. Then src k/v fp16
// via 3-buffer cp.async ring, one barrier per edge (R12 structure).
// Group accounting: dst = group A; stage(0)=B, stage(1)=C committed after the
// sort barrier; cp_wait<2> (or <1> if deg==1) retires A before sq/skd reads.
#define SORT_CAP 128
#define HROW 136   // half row stride: 272 B = 17*16B (cp.async-aligned)
__global__ __launch_bounds__(128)
void node_attn_kernel(const int* __restrict__ off, const int* __restrict__ csr,
                      const float* __restrict__ dstproj,
                      const __half* __restrict__ srcproj,
                      __half* __restrict__ gsum) {
    __shared__ float  sq[8][132];
    __shared__ float  skd[8][132];
    __shared__ float  svd[8][132];
    __shared__ __half sks[3][8][HROW];
    __shared__ __half svs[3][8][HROW];
    __shared__ int    elist[SORT_CAP];

    const int n = blockIdx.x;
    const int t = threadIdx.x;
    const int off0 = off[n];
    const int deg  = off[n + 1] - off0;
    if (deg == 0) return;

    // ---- group A: dst q/k/v stage (in flight during elist load + sort) ----
    const float* dp = dstproj + (size_t)n * (NS * 384);
    for (int i = t; i < 256; i += 128) {
        int s = i >> 5, c = i & 31;
        cp_async16(&sq[s][c * 4],  dp + s * 384 + c * 4);
        cp_async16(&skd[s][c * 4], dp + s * 384 + 128 + c * 4);
        cp_async16(&svd[s][c * 4], dp + s * 384 + 256 + c * 4);
    }
    cp_commit();

    const bool cached = (deg <= SORT_CAP);
    if (cached) {
        for (int i = t; i < deg; i += 128) elist[i] = csr[off0 + i];
        __syncthreads();
        if (t == 0) {    // sort for deterministic accumulation order
            for (int i = 1; i < deg; i++) {
                int v = elist[i], j = i - 1;
                while (j >= 0 && elist[j] > v) { elist[j + 1] = elist[j]; j--; }
                elist[j + 1] = v;
            }
        }
    }
    __syncthreads();    // sorted elist visible

    const int srow = t >> 4;         // 0..7
    const int schk = t & 15;         // 0..15 (16B chunks of 8 halfs)
    auto stage = [&](int e) {
        int sn = cached ? elist[e] : csr[off0 + e];
        const __half* sp = srcproj + (size_t)sn * (NS * 256);
        const int b = e % 3;
        cp_async16(&sks[b][srow][schk * 8], sp + srow * 256 + schk * 8);
        cp_async16(&svs[b][srow][schk * 8], sp + srow * 256 + 128 + schk * 8);
        cp_commit();
    };

    // groups B (edge 0) and C (edge 1)
    stage(0);
    if (deg > 1) { stage(1); cp_wait<2>(); }   // retire A; B,C may fly
    else         { cp_wait<1>(); }             // groups A,B; retire A
    __syncthreads();                           // dst smem visible

    const int p  = t >> 2;     // (head, query) pair 0..31
    const int h  = p >> 3;
    const int qi = p & 7;
    const int g  = t & 3;
    const float scale = 0.17677669529663687f;   // 1/sqrt(32)

    float4 qr[8];
    #pragma unroll
    for (int u = 0; u < 8; u++) qr[u] = *(float4*)(&sq[qi][h * DH + u * 4]);

    // precompute dst-key logits (keys g and g+4), scaled
    float ldl[2];
    #pragma unroll
    for (int j = 0; j < 2; j++) {
        int kk = g + j * 4;
        float acc = 0.f;
        #pragma unroll
        for (int u = 0; u < 8; u++) {
            float4 kr = *(float4*)(&skd[kk][h * DH + u * 4]);
            acc += qr[u].x * kr.x + qr[u].y * kr.y + qr[u].z * kr.z + qr[u].w * kr.w;
        }
        ldl[j] = acc * scale;
    }

    float o[8];
    #pragma unroll
    for (int d = 0; d < 8; d++) o[d] = 0.f;

    const int lbase = (t & 31) & ~3;
    for (int e = 0; e < deg; e++) {
        const int b = e % 3;
        if (e + 1 < deg) cp_wait<1>(); else cp_wait<0>();
        __syncthreads();
        if (e + 2 < deg) stage(e + 2);   // overwrites (e-1)%3 — safe post-barrier

        // src-key logits (keys 8+g, 12+g)
        float l[4];
        l[0] = ldl[0]; l[1] = ldl[1];
        #pragma unroll
        for (int j = 0; j < 2; j++) {
            int kk = g + j * 4;
            const __half* kp = &sks[b][kk][h * DH];
            float acc = 0.f;
            #pragma unroll
            for (int u = 0; u < 8; u++) {
                float2 k0 = __half22float2(*(const __half2*)(kp + u * 4 + 0));
                float2 k1 = __half22float2(*(const __half2*)(kp + u * 4 + 2));
                acc += qr[u].x * k0.x + qr[u].y * k0.y + qr[u].z * k1.x + qr[u].w * k1.y;
            }
            l[2 + j] = acc * scale;
        }

        // softmax over 16 keys (4 local + quad shuffle)
        float m = fmaxf(fmaxf(l[0], l[1]), fmaxf(l[2], l[3]));
        m = fmaxf(m, __shfl_xor_sync(0xffffffffu, m, 1));
        m = fmaxf(m, __shfl_xor_sync(0xffffffffu, m, 2));
        float pr[4], es = 0.f;
        #pragma unroll
        for (int j = 0; j < 4; j++) { pr[j] = __expf(l[j] - m); es += pr[j]; }
        es += __shfl_xor_sync(0xffffffffu, es, 1);
        es += __shfl_xor_sync(0xffffffffu, es, 2);
        float inv = 1.f / es;
        float att[4];
        #pragma unroll
        for (int j = 0; j < 4; j++) att[j] = pr[j] * inv;

        // o += att @ [v_dst (fp32) ; v_src (fp16)]
        #pragma unroll
        for (int kk = 0; kk < 8; kk++) {
            float a = __shfl_sync(0xffffffffu, att[kk >> 2], lbase | (kk & 3));
            const float* vr = &svd[kk][h * DH + g * 8];
            #pragma unroll
            for (int d = 0; d < 8; d++) o[d] += a * vr[d];
        }
        #pragma unroll
        for (int kk = 8; kk < 16; kk++) {
            float a = __shfl_sync(0xffffffffu, att[kk >> 2], lbase | (kk & 3));
            const __half* vr = &svs[b][kk - 8][h * DH + g * 8];
            #pragma unroll
            for (int j = 0; j < 4; j++) {
                float2 v = __half22float2(*(const __half2*)(vr + j * 2));
                o[j * 2 + 0] += a * v.x;
                o[j * 2 + 1] += a * v.y;
            }
        }
    }

    // store fp16 (feeds the fp16 final GEMM)
    __half* outp = gsum + (size_t)n * (NS * DD) + qi * DD + h * DH + g * 8;
    __half2 hs[4];
    hs[0] = __floats2half2_rn(o[0], o[1]);
    hs[1] = __floats2half2_rn(o[2], o[3]);
    hs[2] = __floats2half2_rn(o[4], o[5]);
    hs[3] = __floats2half2_rn(o[6], o[7]);
    *(uint4*)outp = *(uint4*)hs;
}

// ---------------------------------------------------------------------------
extern "C" void kernel_launch(void* const* d_in, const int* in_sizes, int n_in,
                              void* d_out, int out_size) {
    const float* x_a = (const float*)d_in[0];
    const float* x_b = (const float*)d_in[1];
    const int* ei[3] = {(const int*)d_in[2], (const int*)d_in[3], (const int*)d_in[4]};
    const int E  = in_sizes[2] / 2;
    const int Nn = in_sizes[0] / (NS * DD);
    const int M  = Nn * NS;

    float *dstprojB, *cntB, *bfB;
    __half *srcprojB, *sumB, *WfB, *xah, *xbh, *WhB, *WohB;
    int *histB, *offB, *curB, *csrB;
    cudaGetSymbolAddress((void**)&dstprojB, g_dstproj);
    cudaGetSymbolAddress((void**)&srcprojB, g_srcproj);
    cudaGetSymbolAddress((void**)&sumB, g_sum);
    cudaGetSymbolAddress((void**)&cntB, g_cnt);
    cudaGetSymbolAddress((void**)&WfB, g_Wf);
    cudaGetSymbolAddress((void**)&bfB, g_bf);
    cudaGetSymbolAddress((void**)&histB, g_hist);
    cudaGetSymbolAddress((void**)&offB, g_off);
    cudaGetSymbolAddress((void**)&curB, g_cur);
    cudaGetSymbolAddress((void**)&csrB, g_csr);
    cudaGetSymbolAddress((void**)&xah, g_xah);
    cudaGetSymbolAddress((void**)&xbh, g_xbh);
    cudaGetSymbolAddress((void**)&WhB, g_Wh);
    cudaGetSymbolAddress((void**)&WohB, g_Woh);

    static cudaStream_t st[3] = {nullptr, nullptr, nullptr};
    static cudaEvent_t ev0 = nullptr, evDone[3] = {nullptr, nullptr, nullptr};
    static cudaEvent_t evXa = nullptr, evXb = nullptr;
    if (!st[0]) {
        for (int i = 0; i < 3; i++) {
            cudaStreamCreateWithFlags(&st[i], cudaStreamNonBlocking);
            cudaEventCreateWithFlags(&evDone[i], cudaEventDisableTiming);
        }
        cudaEventCreateWithFlags(&ev0, cudaEventDisableTiming);
        cudaEventCreateWithFlags(&evXa, cudaEventDisableTiming);
        cudaEventCreateWithFlags(&evXb, cudaEventDisableTiming);
    }

    float* out = (float*)d_out;

    const __half* xsrcH[3] = {xah, xbh, xah};
    const __half* xdstH[3] = {xbh, xah, xah};
    float* outp[3]  = {out + (size_t)M * DD, out, out};
    float alphav[3] = {1.f, 0.5f, 0.5f};
    int   accumv[3] = {0, 0, 1};

    // fork
    cudaEventRecord(ev0, 0);

    // prefix: convert x_a (st0) and x_b (st1) to fp16 concurrently
    const int n4 = M * DD / 4;
    cudaStreamWaitEvent(st[0], ev0, 0);
    half_kernel<<<(n4 + 255) / 256, 256, 0, st[0]>>>(x_a, xah, n4);
    cudaEventRecord(evXa, st[0]);
    cudaStreamWaitEvent(st[1], ev0, 0);
    half_kernel<<<(n4 + 255) / 256, 256, 0, st[1]>>>(x_b, xbh, n4);
    cudaEventRecord(evXb, st[1]);
    cudaStreamWaitEvent(st[2], ev0, 0);

    for (int r = 0; r < 3; r++) {
        cudaStream_t s = st[r];

        const float* Wb  = (const float*)d_in[5 + r * 6 + 0];
        const float* bb  = (const float*)d_in[5 + r * 6 + 1];
        const float* Win = (const float*)d_in[5 + r * 6 + 2];
        const float* bin = (const float*)d_in[5 + r * 6 + 3];
        const float* Wo  = (const float*)d_in[5 + r * 6 + 4];
        const float* bo  = (const float*)d_in[5 + r * 6 + 5];

        float*  dstproj = dstprojB + (size_t)r * (MAXM * 384);
        __half* srcproj = srcprojB + (size_t)r * (MAXM * 256);
        __half* sum     = sumB     + (size_t)r * (MAXM * DD);
        float*  cnt     = cntB     + (size_t)r * MAXN;
        __half* Wf      = WfB      + (size_t)r * (256 * DD);
        float*  bf      = bfB      + (size_t)r * 256;
        __half* Wh      = WhB      + (size_t)r * (384 * DD);
        __half* Woh     = WohB     + (size_t)r * (DD * DD);
        int*    hist    = histB    + (size_t)r * MAXN;
        int*    off     = offB     + (size_t)r * (MAXN + 1);
        int*    cur     = curB     + (size_t)r * MAXN;
        int*    csr     = csrB     + (size_t)r * MAXE;

        // ---- CSR build + weight prep (independent of x conversion) ----
        zero2_int_kernel<<<(Nn + 255) / 256, 256, 0, s>>>(hist, cur, Nn);
        hist_kernel<<<(E + 255) / 256, 256, 0, s>>>(ei[r], E, hist);
        scan_kernel<<<1, 1024, 0, s>>>(hist, off, Nn);
        scatter_kernel<<<(E + 255) / 256, 256, 0, s>>>(ei[r], E, off, cur, csr);
        cnt_kernel<<<(Nn + 255) / 256, 256, 0, s>>>(off, cnt, Nn);
        fold_kernel<<<128, 256, 0, s>>>(Win, Wb, bb, bin, Wf, bf);
        half_kernel<<<(384 * DD / 4 + 255) / 256, 256, 0, s>>>(Win, Wh, 384 * DD / 4);
        half_kernel<<<(DD * DD / 4 + 255) / 256, 256, 0, s>>>(Wo, Woh, DD * DD / 4);

        // wait for the fp16 x operands this relation needs
        if (r == 0) { cudaStreamWaitEvent(s, evXb, 0); cudaStreamWaitEvent(s, evXa, 0); }
        if (r == 1) { cudaStreamWaitEvent(s, evXa, 0); }
        if (r == 2) { cudaStreamWaitEvent(s, evXa, 0); }

        // per-node projections (dst: q|k|v -> fp32 ; src: folded k|v -> fp16)
        gemm_f16<<<dim3(6, M / 128), 256, 0, s>>>(xdstH[r], Wh, bin, dstproj, 384, nullptr, 1.f, 0, 0);
        gemm_f16<<<dim3(4, M / 128), 256, 0, s>>>(xsrcH[r], Wf, bf, srcproj, 256, nullptr, 1.f, 0, 1);

        // grouped per-node attention + direct segment sum (no atomics)
        node_attn_kernel<<<Nn, 128, 0, s>>>(off, csr, dstproj, srcproj, sum);

        // r2 accumulates into out[0] after r1's plain write
        if (r == 2) cudaStreamWaitEvent(s, evDone[1], 0);

        // mean + Wo + bias (+combine across relations)
        gemm_f16<<<dim3(2, M / 128), 256, 0, s>>>(sum, Woh, bo, outp[r], DD, cnt, alphav[r], accumv[r], 0);

        cudaEventRecord(evDone[r], s);
    }

    // join
    for (int r = 0; r < 3; r++) cudaStreamWaitEvent(0, evDone[r], 0);
}